// round 15
// baseline (speedup 1.0000x reference)
#include <cuda_runtime.h>
#include <cuda_fp16.h>
#include <cstdint>

#define N_NODES 50000
#define N_EDGES 800000
#define D 128
#define R 4
#define NSEG (N_NODES * R)      // 200000
#define NLAYER 3
#define KTOT 640                // R*D + D
#define NTILES 782              // M=64 tiles
#define NCHUNK 10               // K chunks of 64 fp16 (128B rows)

// ---------------- static device scratch ----------------
__device__ __align__(16) __half g_self0[(size_t)N_NODES * D];     // fp16 activations ping
__device__ __align__(16) __half g_self1[(size_t)N_NODES * D];     // fp16 activations pong
__device__ __align__(16) __half g_bh[(size_t)NLAYER * D * KTOT];  // B fp16 [l][n][k]
__device__ float g_x1[(size_t)N_NODES * D];
__device__ float g_x2[(size_t)N_NODES * D];
__device__ int   g_cnt[NSEG];
__device__ int   g_off[NSEG + 1];
__device__ int   g_cursor[NSEG];
__device__ int   g_bsum[256];
__device__ int   g_srcs[N_EDGES];

// ---------------- helpers ----------------
__device__ __forceinline__ uint32_t smem_to_u32(const void* p) {
    uint32_t a;
    asm("{ .reg .u64 t; cvta.to.shared.u64 t, %1; cvt.u32.u64 %0, t; }"
        : "=r"(a) : "l"(p));
    return a;
}

#define CP16(sm, gp) \
    asm volatile("cp.async.cg.shared.global [%0], [%1], 16;" :: "r"(sm), "l"(gp))

__device__ __forceinline__ void ldsm_x4(uint32_t* f, uint32_t addr) {
    asm volatile("ldmatrix.sync.aligned.m8n8.x4.shared.b16 {%0,%1,%2,%3}, [%4];"
                 : "=r"(f[0]), "=r"(f[1]), "=r"(f[2]), "=r"(f[3]) : "r"(addr));
}

__device__ __forceinline__ void mma16816(float* d, const uint32_t* a,
                                         uint32_t b0, uint32_t b1) {
    asm volatile(
        "mma.sync.aligned.m16n8k16.row.col.f32.f16.f16.f32 "
        "{%0,%1,%2,%3}, {%4,%5,%6,%7}, {%8,%9}, {%0,%1,%2,%3};"
        : "+f"(d[0]), "+f"(d[1]), "+f"(d[2]), "+f"(d[3])
        : "r"(a[0]), "r"(a[1]), "r"(a[2]), "r"(a[3]), "r"(b0), "r"(b1));
}

// ---------------- CSR build ----------------
__global__ void k_zero_cnt() {
    int i = blockIdx.x * blockDim.x + threadIdx.x;
    if (i < NSEG) g_cnt[i] = 0;
}

__global__ void k_hist(const int* __restrict__ dst, const int* __restrict__ et) {
    int e = blockIdx.x * blockDim.x + threadIdx.x;
    if (e < N_EDGES) atomicAdd(&g_cnt[dst[e] * R + et[e]], 1);
}

__global__ void k_scan1() {
    __shared__ int sh[1024];
    int t = threadIdx.x;
    int i = blockIdx.x * 1024 + t;
    int v = (i < NSEG) ? g_cnt[i] : 0;
    sh[t] = v;
    __syncthreads();
    for (int d = 1; d < 1024; d <<= 1) {
        int add = (t >= d) ? sh[t - d] : 0;
        __syncthreads();
        sh[t] += add;
        __syncthreads();
    }
    if (i < NSEG) g_off[i] = sh[t] - v;
    if (t == 1023) g_bsum[blockIdx.x] = sh[1023];
}

__global__ void k_scan23(int nb) {
    __shared__ int sh[256];
    int t = threadIdx.x;
    if (t < 256) sh[t] = (t < nb) ? g_bsum[t] : 0;
    __syncthreads();
    for (int d = 1; d < 256; d <<= 1) {
        int add = 0;
        if (t < 256 && t >= d) add = sh[t - d];
        __syncthreads();
        if (t < 256) sh[t] += add;
        __syncthreads();
    }
    int boff = (blockIdx.x > 0) ? sh[blockIdx.x - 1] : 0;
    int i = blockIdx.x * 1024 + t;
    if (i < NSEG) {
        int o = g_off[i] + boff;
        g_off[i] = o;
        g_cursor[i] = o;
    }
    if (i == 0) g_off[NSEG] = N_EDGES;
}

__global__ void k_scatter(const int* __restrict__ src, const int* __restrict__ dst,
                          const int* __restrict__ et) {
    int e = blockIdx.x * blockDim.x + threadIdx.x;
    if (e < N_EDGES) {
        int seg = dst[e] * R + et[e];
        int pos = atomicAdd(&g_cursor[seg], 1);
        g_srcs[pos] = src[e];
    }
}

// ---------------- weight prep: transpose + fp16 ----------------
__global__ void k_bprep(const float* __restrict__ W, const float* __restrict__ root) {
    int i = blockIdx.x * 256 + threadIdx.x;     // over NLAYER*D*KTOT
    if (i >= NLAYER * D * KTOT) return;
    int k = i % KTOT;
    int t = i / KTOT;
    int n = t % D;
    int l = t / D;
    float w;
    if (k < 512) {
        int r = k >> 7, din = k & 127;
        w = W[(((size_t)l * R + r) * D + din) * D + n];
    } else {
        w = root[((size_t)l * D + (k - 512)) * D + n];
    }
    g_bh[i] = __float2half_rn(w);
}

// ---------------- fp16 activations for layer 0 ----------------
__global__ void k_convx(const float* __restrict__ x) {
    int row = blockIdx.x * 8 + (threadIdx.x >> 5);
    if (row >= N_NODES) return;
    int lane = threadIdx.x & 31;
    float4 v = *reinterpret_cast<const float4*>(x + (size_t)row * D + lane * 4);
    __half h[4];
    h[0] = __float2half_rn(v.x);
    h[1] = __float2half_rn(v.y);
    h[2] = __float2half_rn(v.z);
    h[3] = __float2half_rn(v.w);
    *reinterpret_cast<uint2*>(&g_self0[(size_t)row * D + lane * 4]) =
        *reinterpret_cast<uint2*>(h);
}

// ---------------- fused layer: smem agg + HMMA GEMM + relu/residual/LN ----------------
// smem: [0:512) bias, [512:1024) gamma, [1024:1536) beta
//       A tile resident: 2048 + chunk*8192, 10 chunks (64 rows x 128B, SW128)  = 81920
//       B tile (single buffered): 2048 + 81920 = 83968, 16384 bytes
//       LN partials reuse A chunk 0 after mainloop: sSum[64][2]@2048, sSq@2560
#define SMEM_DYN (2048 + NCHUNK * 8192 + 16384)   // 100352 -> 2 CTAs/SM

__global__ void __launch_bounds__(256, 2) k_layer(
    int layer, const float* __restrict__ bias,
    const float* __restrict__ gamma, const float* __restrict__ beta,
    const float* __restrict__ xin, float* __restrict__ xout,
    const __half* __restrict__ self_in, __half* __restrict__ self_out,
    int write_next) {
    extern __shared__ char smem[];
    float* sBias  = (float*)smem;
    float* sGamma = (float*)(smem + 512);
    float* sBeta  = (float*)(smem + 1024);
    uint32_t smem_u = smem_to_u32(smem);
    int tid = threadIdx.x;
    int wid = tid >> 5;
    int lane = tid & 31;
    int brow = blockIdx.x * 64;

    const uint32_t bBase = smem_u + 2048 + NCHUNK * 8192;
    const __half* bh = g_bh + (size_t)layer * D * KTOT;

    auto load_B = [&](int c) {
        int kcol = c * 64;
#pragma unroll
        for (int it = 0; it < 4; it++) {
            int u = tid + it * 256;          // 0..1023 -> 128 rows
            int row = u >> 3;
            int c16 = u & 7;
            uint32_t off = row * 128 + c16 * 16;
            uint32_t sw = off ^ ((off >> 3) & 0x70);
            CP16(bBase + sw, &bh[(size_t)row * KTOT + kcol + c16 * 8]);
        }
        asm volatile("cp.async.commit_group;" ::: "memory");
    };

    if (tid < 32) {
        *reinterpret_cast<float4*>(&sBias[tid * 4]) =
            *reinterpret_cast<const float4*>(bias + tid * 4);
        *reinterpret_cast<float4*>(&sGamma[tid * 4]) =
            *reinterpret_cast<const float4*>(gamma + tid * 4);
        *reinterpret_cast<float4*>(&sBeta[tid * 4]) =
            *reinterpret_cast<const float4*>(beta + tid * 4);
    }
    load_B(0);   // overlaps with the agg phase below

    // ---- agg phase: each warp aggregates 32 segments into resident A smem ----
    // lane l covers relation-cols [4l, 4l+4) -> chunk 2r + (l>>4), byte (l&15)*8
    int cstride_sel = (lane >> 4);          // 0 or 1
    int cbyte = (lane & 15) * 8;
    {
        int seg0 = blockIdx.x * 256 + wid * 32;
        for (int sidx = 0; sidx < 32; sidx++) {
            int seg = seg0 + sidx;
            int node = seg >> 2;
            if (node >= N_NODES) break;
            int r = seg & 3;
            int lrow = node - brow;          // 0..63
            int beg = g_off[seg];
            int end = g_off[seg + 1];
            float ax = 0.f, ay = 0.f, az = 0.f, aw = 0.f;
            for (int j = beg; j < end; j++) {
                int sn = g_srcs[j];
                uint2 raw = *reinterpret_cast<const uint2*>(
                    &self_in[(size_t)sn * D + lane * 4]);
                __half2 h01 = *reinterpret_cast<__half2*>(&raw.x);
                __half2 h23 = *reinterpret_cast<__half2*>(&raw.y);
                float2 f01 = __half22float2(h01);
                float2 f23 = __half22float2(h23);
                ax += f01.x; ay += f01.y; az += f23.x; aw += f23.y;
            }
            float inv = (end > beg) ? 1.0f / (float)(end - beg) : 0.0f;
            __half h[4];
            h[0] = __float2half_rn(ax * inv);
            h[1] = __float2half_rn(ay * inv);
            h[2] = __float2half_rn(az * inv);
            h[3] = __float2half_rn(aw * inv);
            uint32_t off = lrow * 128 + cbyte;
            uint32_t sw = off ^ ((off >> 3) & 0x70);
            *reinterpret_cast<uint2*>(smem + 2048 + (2 * r + cstride_sel) * 8192 + sw) =
                *reinterpret_cast<uint2*>(h);
        }
    }
    // ---- self-cols: chunks 8,9 <- self_in rows of this tile ----
    {
#pragma unroll
        for (int rr = wid * 8; rr < wid * 8 + 8; rr++) {
            int row = brow + rr;
            if (row >= N_NODES) break;
            uint2 v = *reinterpret_cast<const uint2*>(
                &self_in[(size_t)row * D + lane * 4]);
            uint32_t off = rr * 128 + cbyte;
            uint32_t sw = off ^ ((off >> 3) & 0x70);
            *reinterpret_cast<uint2*>(smem + 2048 + (8 + cstride_sel) * 8192 + sw) = v;
        }
    }

    // warp tile: 16 (m) x 64 (n); 4 m-tiles x 2 n-tiles
    int wm = wid & 3;
    int wn = wid >> 2;
    int lrow16 = lane & 15;
    int kh16 = (lane >> 4) * 16;

    float acc[8][4];
#pragma unroll
    for (int q = 0; q < 8; q++)
#pragma unroll
        for (int j = 0; j < 4; j++) acc[q][j] = 0.f;

    for (int c = 0; c < NCHUNK; c++) {
        asm volatile("cp.async.wait_group 0;" ::: "memory");
        __syncthreads();              // B(c) visible; (c==0 also fences agg STS)

        uint32_t aBase = smem_u + 2048 + c * 8192;
#pragma unroll
        for (int ks = 0; ks < 4; ks++) {
            int kb = ks * 32 + kh16;
            uint32_t ah[4], bhf[4][4];
            {
                int row = wm * 16 + lrow16;
                uint32_t off = row * 128 + kb;
                ldsm_x4(ah, aBase + (off ^ ((off >> 3) & 0x70)));
            }
#pragma unroll
            for (int p = 0; p < 4; p++) {
                int row = wn * 64 + p * 16 + lrow16;
                uint32_t off = row * 128 + kb;
                ldsm_x4(bhf[p], bBase + (off ^ ((off >> 3) & 0x70)));
            }
#pragma unroll
            for (int p = 0; p < 4; p++) {
                mma16816(acc[2 * p + 0], ah, bhf[p][0], bhf[p][2]);
                mma16816(acc[2 * p + 1], ah, bhf[p][1], bhf[p][3]);
            }
        }
        __syncthreads();                         // all warps done with B(c)
        if (c + 1 < NCHUNK) load_B(c + 1);       // refill single B buffer
    }
    // A chunk 0 smem dead after mainloop -> reuse for LN partials

    float* sSum = (float*)(smem + 2048);   // [64][2]
    float* sSq  = (float*)(smem + 2560);   // [64][2]

    // ---- relu + residual; per-row partials ----
    int r0 = brow + wm * 16 + (lane >> 2);
    int r1 = r0 + 8;
    float s0 = 0.f, s1 = 0.f, q0 = 0.f, q1 = 0.f;
#pragma unroll
    for (int q = 0; q < 8; q++) {
        int col = wn * 64 + (q >> 1) * 16 + (q & 1) * 8 + 2 * (lane & 3);
        float bx = sBias[col], by = sBias[col + 1];
        float2 x0 = (r0 < N_NODES)
            ? *reinterpret_cast<const float2*>(xin + (size_t)r0 * D + col)
            : make_float2(0.f, 0.f);
        float2 x1 = (r1 < N_NODES)
            ? *reinterpret_cast<const float2*>(xin + (size_t)r1 * D + col)
            : make_float2(0.f, 0.f);
        float v0 = fmaxf(acc[q][0] + bx, 0.f) + x0.x;
        float v1 = fmaxf(acc[q][1] + by, 0.f) + x0.y;
        float v2 = fmaxf(acc[q][2] + bx, 0.f) + x1.x;
        float v3 = fmaxf(acc[q][3] + by, 0.f) + x1.y;
        acc[q][0] = v0; acc[q][1] = v1;
        acc[q][2] = v2; acc[q][3] = v3;
        s0 += v0 + v1;  q0 += v0 * v0 + v1 * v1;
        s1 += v2 + v3;  q1 += v2 * v2 + v3 * v3;
    }
    s0 += __shfl_xor_sync(0xFFFFFFFFu, s0, 1);
    s0 += __shfl_xor_sync(0xFFFFFFFFu, s0, 2);
    s1 += __shfl_xor_sync(0xFFFFFFFFu, s1, 1);
    s1 += __shfl_xor_sync(0xFFFFFFFFu, s1, 2);
    q0 += __shfl_xor_sync(0xFFFFFFFFu, q0, 1);
    q0 += __shfl_xor_sync(0xFFFFFFFFu, q0, 2);
    q1 += __shfl_xor_sync(0xFFFFFFFFu, q1, 1);
    q1 += __shfl_xor_sync(0xFFFFFFFFu, q1, 2);
    if ((lane & 3) == 0) {
        int m0 = wm * 16 + (lane >> 2);
        sSum[m0 * 2 + wn] = s0;
        sSum[(m0 + 8) * 2 + wn] = s1;
        sSq[m0 * 2 + wn] = q0;
        sSq[(m0 + 8) * 2 + wn] = q1;
    }
    __syncthreads();

    // ---- LN + write xout (+ fp16 self activations for next layer) ----
    int m0 = wm * 16 + (lane >> 2);
#pragma unroll
    for (int h = 0; h < 2; h++) {
        int m = m0 + h * 8;
        int row = brow + m;
        if (row >= N_NODES) continue;
        float s = sSum[m * 2 + 0] + sSum[m * 2 + 1];
        float sq = sSq[m * 2 + 0] + sSq[m * 2 + 1];
        float mean = s * (1.0f / 128.0f);
        float var = sq * (1.0f / 128.0f) - mean * mean;
        float rs = rsqrtf(var + 1e-5f);
#pragma unroll
        for (int q = 0; q < 8; q++) {
            int col = wn * 64 + (q >> 1) * 16 + (q & 1) * 8 + 2 * (lane & 3);
            float o0 = (acc[q][2 * h + 0] - mean) * rs * sGamma[col] + sBeta[col];
            float o1 = (acc[q][2 * h + 1] - mean) * rs * sGamma[col + 1] + sBeta[col + 1];
            *reinterpret_cast<float2*>(xout + (size_t)row * D + col) =
                make_float2(o0, o1);
            if (write_next) {
                __half2 hp = __floats2half2_rn(o0, o1);
                *reinterpret_cast<__half2*>(&self_out[(size_t)row * D + col]) = hp;
            }
        }
    }
}

// ---------------- host launcher ----------------
extern "C" void kernel_launch(void* const* d_in, const int* in_sizes, int n_in,
                              void* d_out, int out_size) {
    const float* x     = (const float*)d_in[0];
    const int*   ei    = (const int*)d_in[1];
    const int*   et    = (const int*)d_in[2];
    const float* W     = (const float*)d_in[3];
    const float* root  = (const float*)d_in[4];
    const float* bias  = (const float*)d_in[5];
    const float* gamma = (const float*)d_in[6];
    const float* beta  = (const float*)d_in[7];
    float* out = (float*)d_out;

    const int* src = ei;
    const int* dst = ei + N_EDGES;

    float *px1 = nullptr, *px2 = nullptr;
    __half *ps0 = nullptr, *ps1 = nullptr;
    cudaGetSymbolAddress((void**)&px1, g_x1);
    cudaGetSymbolAddress((void**)&px2, g_x2);
    cudaGetSymbolAddress((void**)&ps0, g_self0);
    cudaGetSymbolAddress((void**)&ps1, g_self1);

    cudaFuncSetAttribute(k_layer, cudaFuncAttributeMaxDynamicSharedMemorySize, SMEM_DYN);

    // CSR build (edge structure is layer-invariant)
    k_zero_cnt<<<(NSEG + 255) / 256, 256>>>();
    k_hist<<<(N_EDGES + 255) / 256, 256>>>(dst, et);
    int nb = (NSEG + 1023) / 1024;
    k_scan1<<<nb, 1024>>>();
    k_scan23<<<nb, 1024>>>(nb);
    k_scatter<<<(N_EDGES + 255) / 256, 256>>>(src, dst, et);

    // weight transpose + fp16
    k_bprep<<<(NLAYER * D * KTOT + 255) / 256, 256>>>(W, root);
    // fp16 activations for layer 0
    k_convx<<<(N_NODES + 7) / 8, 256>>>(x);

    const float* xin = x;
    for (int l = 0; l < NLAYER; l++) {
        float* xout = (l == NLAYER - 1) ? out : ((l == 0) ? px1 : px2);
        const __half* sin = (l & 1) ? ps1 : ps0;
        __half* sout = (l & 1) ? ps0 : ps1;
        k_layer<<<NTILES, 256, SMEM_DYN>>>(l, bias + (size_t)l * D,
                                           gamma + (size_t)l * D,
                                           beta + (size_t)l * D,
                                           xin, xout, sin, sout,
                                           l < NLAYER - 1 ? 1 : 0);
        xin = xout;
    }
}

// round 16
// speedup vs baseline: 1.4577x; 1.4577x over previous
#include <cuda_runtime.h>
#include <cuda_fp16.h>
#include <cstdint>

#define N_NODES 50000
#define N_EDGES 800000
#define D 128
#define R 4
#define NSEG (N_NODES * R)      // 200000
#define NLAYER 3
#define KTOT 640                // R*D + D
#define MPAD 50048              // 391 * 128
#define NTILES 391
#define NCHUNK 10               // K chunks of 64 fp16 (128B rows)

// ---------------- static device scratch ----------------
__device__ __align__(16) __half g_ah[(size_t)MPAD * KTOT];        // A fp16 [node][640]
__device__ __align__(16) __half g_bh[(size_t)NLAYER * D * KTOT];  // B fp16 [l][n][k]
__device__ float g_x1[(size_t)N_NODES * D];
__device__ float g_x2[(size_t)N_NODES * D];
__device__ int   g_cnt[NSEG];     // zero-initialized; re-zeroed by k_scan23 each run
__device__ int   g_off[NSEG + 1];
__device__ int   g_cursor[NSEG];
__device__ int   g_bsum[256];
__device__ int   g_srcs[N_EDGES];

// ---------------- helpers ----------------
__device__ __forceinline__ uint32_t smem_to_u32(const void* p) {
    uint32_t a;
    asm("{ .reg .u64 t; cvta.to.shared.u64 t, %1; cvt.u32.u64 %0, t; }"
        : "=r"(a) : "l"(p));
    return a;
}

#define CP16(sm, gp) \
    asm volatile("cp.async.cg.shared.global [%0], [%1], 16;" :: "r"(sm), "l"(gp))

__device__ __forceinline__ void ldsm_x4(uint32_t* f, uint32_t addr) {
    asm volatile("ldmatrix.sync.aligned.m8n8.x4.shared.b16 {%0,%1,%2,%3}, [%4];"
                 : "=r"(f[0]), "=r"(f[1]), "=r"(f[2]), "=r"(f[3]) : "r"(addr));
}

__device__ __forceinline__ void mma16816(float* d, const uint32_t* a,
                                         uint32_t b0, uint32_t b1) {
    asm volatile(
        "mma.sync.aligned.m16n8k16.row.col.f32.f16.f16.f32 "
        "{%0,%1,%2,%3}, {%4,%5,%6,%7}, {%8,%9}, {%0,%1,%2,%3};"
        : "+f"(d[0]), "+f"(d[1]), "+f"(d[2]), "+f"(d[3])
        : "r"(a[0]), "r"(a[1]), "r"(a[2]), "r"(a[3]), "r"(b0), "r"(b1));
}

// ---------------- CSR build ----------------
__global__ void k_hist(const int* __restrict__ dst, const int* __restrict__ et) {
    int e = blockIdx.x * blockDim.x + threadIdx.x;
    if (e < N_EDGES) atomicAdd(&g_cnt[dst[e] * R + et[e]], 1);
}

__global__ void k_scan1() {
    __shared__ int sh[1024];
    int t = threadIdx.x;
    int i = blockIdx.x * 1024 + t;
    int v = (i < NSEG) ? g_cnt[i] : 0;
    sh[t] = v;
    __syncthreads();
    for (int d = 1; d < 1024; d <<= 1) {
        int add = (t >= d) ? sh[t - d] : 0;
        __syncthreads();
        sh[t] += add;
        __syncthreads();
    }
    if (i < NSEG) g_off[i] = sh[t] - v;
    if (t == 1023) g_bsum[blockIdx.x] = sh[1023];
}

// fused scan2+scan3; also re-zeroes g_cnt (consumed by k_scan1) so the next
// graph replay starts from a clean histogram without a dedicated zero kernel.
__global__ void k_scan23(int nb) {
    __shared__ int sh[256];
    int t = threadIdx.x;
    if (t < 256) sh[t] = (t < nb) ? g_bsum[t] : 0;
    __syncthreads();
    for (int d = 1; d < 256; d <<= 1) {
        int add = 0;
        if (t < 256 && t >= d) add = sh[t - d];
        __syncthreads();
        if (t < 256) sh[t] += add;
        __syncthreads();
    }
    int boff = (blockIdx.x > 0) ? sh[blockIdx.x - 1] : 0;
    int i = blockIdx.x * 1024 + t;
    if (i < NSEG) {
        int o = g_off[i] + boff;
        g_off[i] = o;
        g_cursor[i] = o;
        g_cnt[i] = 0;                 // self-clean for next replay
    }
    if (i == 0) g_off[NSEG] = N_EDGES;
}

__global__ void k_scatter(const int* __restrict__ src, const int* __restrict__ dst,
                          const int* __restrict__ et) {
    int e = blockIdx.x * blockDim.x + threadIdx.x;
    if (e < N_EDGES) {
        int seg = dst[e] * R + et[e];
        int pos = atomicAdd(&g_cursor[seg], 1);
        g_srcs[pos] = src[e];
    }
}

// ---------------- weight prep: transpose + fp16 ----------------
__global__ void k_bprep(const float* __restrict__ W, const float* __restrict__ root) {
    int i = blockIdx.x * 256 + threadIdx.x;     // over NLAYER*D*KTOT
    if (i >= NLAYER * D * KTOT) return;
    int k = i % KTOT;
    int t = i / KTOT;
    int n = t % D;
    int l = t / D;
    float w;
    if (k < 512) {
        int r = k >> 7, din = k & 127;
        w = W[(((size_t)l * R + r) * D + din) * D + n];
    } else {
        w = root[((size_t)l * D + (k - 512)) * D + n];
    }
    g_bh[i] = __float2half_rn(w);
}

// ---------------- fill self-columns (512..639) of A from fp32 activations ----------------
__global__ void k_convx(const float* __restrict__ x) {
    int row = blockIdx.x * 8 + (threadIdx.x >> 5);
    if (row >= N_NODES) return;
    int lane = threadIdx.x & 31;
    float4 v = *reinterpret_cast<const float4*>(x + (size_t)row * D + lane * 4);
    __half h[4];
    h[0] = __float2half_rn(v.x);
    h[1] = __float2half_rn(v.y);
    h[2] = __float2half_rn(v.z);
    h[3] = __float2half_rn(v.w);
    size_t o = (size_t)row * KTOT + 512 + lane * 4;
    *reinterpret_cast<uint2*>(&g_ah[o]) = *reinterpret_cast<uint2*>(h);
}

// ---------------- segment-mean aggregation: 2 interleaved segments per warp ----------------
__global__ void k_agg() {
    int w = blockIdx.x * 8 + (threadIdx.x >> 5);
    int segA = w * 2;
    if (segA >= NSEG) return;
    int segB = segA + 1;                // NSEG even -> always valid
    int lane = threadIdx.x & 31;
    int jA = g_off[segA], eA = g_off[segA + 1];
    int jB = g_off[segB], eB = g_off[segB + 1];
    int cA = eA - jA, cB = eB - jB;
    float a0 = 0.f, a1 = 0.f, a2 = 0.f, a3 = 0.f;
    float b0 = 0.f, b1 = 0.f, b2 = 0.f, b3 = 0.f;

    // interleaved main loop: two independent gather chains in flight
    while (jA < eA && jB < eB) {
        int snA = g_srcs[jA];
        int snB = g_srcs[jB];
        uint2 rA = *reinterpret_cast<const uint2*>(
            &g_ah[(size_t)snA * KTOT + 512 + lane * 4]);
        uint2 rB = *reinterpret_cast<const uint2*>(
            &g_ah[(size_t)snB * KTOT + 512 + lane * 4]);
        float2 fA0 = __half22float2(*reinterpret_cast<__half2*>(&rA.x));
        float2 fA1 = __half22float2(*reinterpret_cast<__half2*>(&rA.y));
        float2 fB0 = __half22float2(*reinterpret_cast<__half2*>(&rB.x));
        float2 fB1 = __half22float2(*reinterpret_cast<__half2*>(&rB.y));
        a0 += fA0.x; a1 += fA0.y; a2 += fA1.x; a3 += fA1.y;
        b0 += fB0.x; b1 += fB0.y; b2 += fB1.x; b3 += fB1.y;
        jA++; jB++;
    }
    while (jA < eA) {
        int sn = g_srcs[jA++];
        uint2 r = *reinterpret_cast<const uint2*>(
            &g_ah[(size_t)sn * KTOT + 512 + lane * 4]);
        float2 f0 = __half22float2(*reinterpret_cast<__half2*>(&r.x));
        float2 f1 = __half22float2(*reinterpret_cast<__half2*>(&r.y));
        a0 += f0.x; a1 += f0.y; a2 += f1.x; a3 += f1.y;
    }
    while (jB < eB) {
        int sn = g_srcs[jB++];
        uint2 r = *reinterpret_cast<const uint2*>(
            &g_ah[(size_t)sn * KTOT + 512 + lane * 4]);
        float2 f0 = __half22float2(*reinterpret_cast<__half2*>(&r.x));
        float2 f1 = __half22float2(*reinterpret_cast<__half2*>(&r.y));
        b0 += f0.x; b1 += f0.y; b2 += f1.x; b3 += f1.y;
    }

    float invA = (cA > 0) ? 1.0f / (float)cA : 0.0f;
    float invB = (cB > 0) ? 1.0f / (float)cB : 0.0f;
    __half hA[4], hB[4];
    hA[0] = __float2half_rn(a0 * invA);
    hA[1] = __float2half_rn(a1 * invA);
    hA[2] = __float2half_rn(a2 * invA);
    hA[3] = __float2half_rn(a3 * invA);
    hB[0] = __float2half_rn(b0 * invB);
    hB[1] = __float2half_rn(b1 * invB);
    hB[2] = __float2half_rn(b2 * invB);
    hB[3] = __float2half_rn(b3 * invB);
    {
        int node = segA >> 2, r = segA & 3;
        *reinterpret_cast<uint2*>(&g_ah[(size_t)node * KTOT + r * 128 + lane * 4]) =
            *reinterpret_cast<uint2*>(hA);
    }
    {
        int node = segB >> 2, r = segB & 3;
        *reinterpret_cast<uint2*>(&g_ah[(size_t)node * KTOT + r * 128 + lane * 4]) =
            *reinterpret_cast<uint2*>(hB);
    }
}

// ---------------- HMMA GEMM + fused relu/residual/LayerNorm, occupancy-2 ----------------
// smem: [0:512) bias, [512:1024) gamma, [1024:1536) beta
//       A tiles (double buffered): 2048 + buf*16384
//       B tile (single buffered):  2048 + 32768
//       LN row partials (post-mainloop, reuse tile area): 2048 sSum[128][2], 3072 sSq[128][2]
#define SMEM_DYN (2048 + 2 * 16384 + 16384)   // 51200 -> 2 CTAs/SM

__global__ void __launch_bounds__(256, 2) k_gemm(int layer, const float* __restrict__ bias,
                                                 const float* __restrict__ gamma,
                                                 const float* __restrict__ beta,
                                                 const float* __restrict__ xin,
                                                 float* __restrict__ xout,
                                                 int write_next) {
    extern __shared__ char smem[];
    float* sBias  = (float*)smem;
    float* sGamma = (float*)(smem + 512);
    float* sBeta  = (float*)(smem + 1024);
    uint32_t smem_u = smem_to_u32(smem);
    int tid = threadIdx.x;
    int wid = tid >> 5;
    int lane = tid & 31;
    int brow = blockIdx.x * 128;

    if (tid < 32) {
        *reinterpret_cast<float4*>(&sBias[tid * 4]) =
            *reinterpret_cast<const float4*>(bias + tid * 4);
        *reinterpret_cast<float4*>(&sGamma[tid * 4]) =
            *reinterpret_cast<const float4*>(gamma + tid * 4);
        *reinterpret_cast<float4*>(&sBeta[tid * 4]) =
            *reinterpret_cast<const float4*>(beta + tid * 4);
    }

    const __half* bh = g_bh + (size_t)layer * D * KTOT;

    // warp tile: 32 (m) x 64 (n)
    int wm = wid & 3;            // m0 = wm*32
    int wn = wid >> 2;           // n0 = wn*64
    int lrow = lane & 15;
    int kh16 = (lane >> 4) * 16;

    const uint32_t bBase = smem_u + 2048 + 32768;

    float acc[2][8][4];
#pragma unroll
    for (int t = 0; t < 2; t++)
#pragma unroll
        for (int q = 0; q < 8; q++)
#pragma unroll
            for (int j = 0; j < 4; j++) acc[t][q][j] = 0.f;

    auto load_A = [&](int c, int buf) {
        uint32_t base = smem_u + 2048 + buf * 16384;
        int kcol = c * 64;
#pragma unroll
        for (int it = 0; it < 4; it++) {
            int u = tid + it * 256;          // 0..1023
            int row = u >> 3;                // 0..127
            int c16 = u & 7;
            uint32_t off = row * 128 + c16 * 16;
            uint32_t sw = off ^ ((off >> 3) & 0x70);
            CP16(base + sw, &g_ah[(size_t)(brow + row) * KTOT + kcol + c16 * 8]);
        }
        asm volatile("cp.async.commit_group;" ::: "memory");
    };
    auto load_B = [&](int c) {
        int kcol = c * 64;
#pragma unroll
        for (int it = 0; it < 4; it++) {
            int u = tid + it * 256;          // 0..1023 -> full 128 rows
            int row = u >> 3;
            int c16 = u & 7;
            uint32_t off = row * 128 + c16 * 16;
            uint32_t sw = off ^ ((off >> 3) & 0x70);
            CP16(bBase + sw, &bh[(size_t)row * KTOT + kcol + c16 * 8]);
        }
        asm volatile("cp.async.commit_group;" ::: "memory");
    };

    load_A(0, 0);
    load_B(0);

    for (int c = 0; c < NCHUNK; c++) {
        asm volatile("cp.async.wait_group 0;" ::: "memory");
        __syncthreads();
        if (c + 1 < NCHUNK) load_A(c + 1, (c + 1) & 1);   // A buffer (c+1)&1 is free

        uint32_t base = smem_u + 2048 + (c & 1) * 16384;
#pragma unroll
        for (int ks = 0; ks < 4; ks++) {
            int kb = ks * 32 + kh16;
            uint32_t ah[2][4], bhf[4][4];
#pragma unroll
            for (int t = 0; t < 2; t++) {
                int row = wm * 32 + t * 16 + lrow;
                uint32_t off = row * 128 + kb;
                ldsm_x4(ah[t], base + (off ^ ((off >> 3) & 0x70)));
            }
#pragma unroll
            for (int p = 0; p < 4; p++) {
                int row = wn * 64 + p * 16 + lrow;
                uint32_t off = row * 128 + kb;
                ldsm_x4(bhf[p], bBase + (off ^ ((off >> 3) & 0x70)));
            }
#pragma unroll
            for (int t = 0; t < 2; t++)
#pragma unroll
                for (int p = 0; p < 4; p++) {
                    mma16816(acc[t][2 * p + 0], ah[t], bhf[p][0], bhf[p][2]);
                    mma16816(acc[t][2 * p + 1], ah[t], bhf[p][1], bhf[p][3]);
                }
        }
        __syncthreads();                         // all warps done with B(c)
        if (c + 1 < NCHUNK) load_B(c + 1);       // refill single B buffer
    }
    // tile smem dead after final sync -> reuse for LN partials

    float* sSum = (float*)(smem + 2048);   // [128][2]
    float* sSq  = (float*)(smem + 3072);   // [128][2]

    // ---- step 1: v = relu(acc + bias) + xin ; per-row partials ----
    float psum[2][2], psq[2][2];
#pragma unroll
    for (int t = 0; t < 2; t++) {
        int r0 = brow + wm * 32 + t * 16 + (lane >> 2);
        int r1 = r0 + 8;
        float s0 = 0.f, s1 = 0.f, q0 = 0.f, q1 = 0.f;
#pragma unroll
        for (int q = 0; q < 8; q++) {
            int col = wn * 64 + (q >> 1) * 16 + (q & 1) * 8 + 2 * (lane & 3);
            float bx = sBias[col], by = sBias[col + 1];
            float2 x0 = (r0 < N_NODES)
                ? *reinterpret_cast<const float2*>(xin + (size_t)r0 * D + col)
                : make_float2(0.f, 0.f);
            float2 x1 = (r1 < N_NODES)
                ? *reinterpret_cast<const float2*>(xin + (size_t)r1 * D + col)
                : make_float2(0.f, 0.f);
            float v0 = fmaxf(acc[t][q][0] + bx, 0.f) + x0.x;
            float v1 = fmaxf(acc[t][q][1] + by, 0.f) + x0.y;
            float v2 = fmaxf(acc[t][q][2] + bx, 0.f) + x1.x;
            float v3 = fmaxf(acc[t][q][3] + by, 0.f) + x1.y;
            acc[t][q][0] = v0; acc[t][q][1] = v1;
            acc[t][q][2] = v2; acc[t][q][3] = v3;
            s0 += v0 + v1;  q0 += v0 * v0 + v1 * v1;
            s1 += v2 + v3;  q1 += v2 * v2 + v3 * v3;
        }
        psum[t][0] = s0; psum[t][1] = s1;
        psq[t][0] = q0;  psq[t][1] = q1;
    }
    // quad reduce (4 threads share each row)
#pragma unroll
    for (int t = 0; t < 2; t++)
#pragma unroll
        for (int h = 0; h < 2; h++) {
            psum[t][h] += __shfl_xor_sync(0xFFFFFFFFu, psum[t][h], 1);
            psum[t][h] += __shfl_xor_sync(0xFFFFFFFFu, psum[t][h], 2);
            psq[t][h]  += __shfl_xor_sync(0xFFFFFFFFu, psq[t][h], 1);
            psq[t][h]  += __shfl_xor_sync(0xFFFFFFFFu, psq[t][h], 2);
        }
    if ((lane & 3) == 0) {
#pragma unroll
        for (int t = 0; t < 2; t++) {
            int m0 = wm * 32 + t * 16 + (lane >> 2);
            sSum[m0 * 2 + wn] = psum[t][0];
            sSum[(m0 + 8) * 2 + wn] = psum[t][1];
            sSq[m0 * 2 + wn] = psq[t][0];
            sSq[(m0 + 8) * 2 + wn] = psq[t][1];
        }
    }
    __syncthreads();

    // ---- step 2: LN + write xout (+ fp16 self-cols for next layer) ----
#pragma unroll
    for (int t = 0; t < 2; t++) {
        int m0 = wm * 32 + t * 16 + (lane >> 2);
#pragma unroll
        for (int h = 0; h < 2; h++) {
            int m = m0 + h * 8;
            int row = brow + m;
            if (row >= N_NODES) continue;
            float s = sSum[m * 2 + 0] + sSum[m * 2 + 1];
            float sq = sSq[m * 2 + 0] + sSq[m * 2 + 1];
            float mean = s * (1.0f / 128.0f);
            float var = sq * (1.0f / 128.0f) - mean * mean;
            float rs = rsqrtf(var + 1e-5f);
#pragma unroll
            for (int q = 0; q < 8; q++) {
                int col = wn * 64 + (q >> 1) * 16 + (q & 1) * 8 + 2 * (lane & 3);
                float o0 = (acc[t][q][2 * h + 0] - mean) * rs * sGamma[col] + sBeta[col];
                float o1 = (acc[t][q][2 * h + 1] - mean) * rs * sGamma[col + 1] + sBeta[col + 1];
                *reinterpret_cast<float2*>(xout + (size_t)row * D + col) =
                    make_float2(o0, o1);
                if (write_next) {
                    __half2 hp = __floats2half2_rn(o0, o1);
                    *reinterpret_cast<__half2*>(
                        &g_ah[(size_t)row * KTOT + 512 + col]) = hp;
                }
            }
        }
    }
}

// ---------------- host launcher ----------------
extern "C" void kernel_launch(void* const* d_in, const int* in_sizes, int n_in,
                              void* d_out, int out_size) {
    const float* x     = (const float*)d_in[0];
    const int*   ei    = (const int*)d_in[1];
    const int*   et    = (const int*)d_in[2];
    const float* W     = (const float*)d_in[3];
    const float* root  = (const float*)d_in[4];
    const float* bias  = (const float*)d_in[5];
    const float* gamma = (const float*)d_in[6];
    const float* beta  = (const float*)d_in[7];
    float* out = (float*)d_out;

    const int* src = ei;
    const int* dst = ei + N_EDGES;

    float *px1 = nullptr, *px2 = nullptr;
    cudaGetSymbolAddress((void**)&px1, g_x1);
    cudaGetSymbolAddress((void**)&px2, g_x2);

    cudaFuncSetAttribute(k_gemm, cudaFuncAttributeMaxDynamicSharedMemorySize, SMEM_DYN);

    // CSR build (edge structure is layer-invariant); g_cnt arrives zeroed
    // (static init on first run, self-cleaned by k_scan23 on every run).
    k_hist<<<(N_EDGES + 255) / 256, 256>>>(dst, et);
    int nb = (NSEG + 1023) / 1024;
    k_scan1<<<nb, 1024>>>();
    k_scan23<<<nb, 1024>>>(nb);
    k_scatter<<<(N_EDGES + 255) / 256, 256>>>(src, dst, et);

    // weight transpose + fp16
    k_bprep<<<(NLAYER * D * KTOT + 255) / 256, 256>>>(W, root);
    // self-cols for layer 0 (must precede first k_agg — it gathers from them)
    k_convx<<<(N_NODES + 7) / 8, 256>>>(x);

    const float* xin = x;
    for (int l = 0; l < NLAYER; l++) {
        k_agg<<<(NSEG / 2 + 7) / 8, 256>>>();
        float* xout = (l == NLAYER - 1) ? out : ((l == 0) ? px1 : px2);
        k_gemm<<<NTILES, 256, SMEM_DYN>>>(l, bias + (size_t)l * D,
                                          gamma + (size_t)l * D,
                                          beta + (size_t)l * D,
                                          xin, xout,
                                          l < NLAYER - 1 ? 1 : 0);
        xin = xout;
    }
}